// round 3
// baseline (speedup 1.0000x reference)
#include <cuda_runtime.h>
#include <cuda_bf16.h>
#include <cstdint>

// ---------------------------------------------------------------------------
// ConvLSTMCell (complex-valued), fused fp32 baseline with f32x2 packed FFMA.
// B=16, C=128 (64r+64i), H=W=64, K=3, SAME padding.
// f-gate is computed by the reference's setup but UNUSED -> skipped entirely.
// ---------------------------------------------------------------------------

#define Bz   16
#define HALF 64
#define ICZ  256      // zr(128) ++ zi(128)
#define HH   64
#define WW   64
#define HWP  4096     // 64*64
#define ZP   66       // padded spatial
#define ZPP  4356     // 66*66
#define NPLANE 6      // i_r,i_i,o_r,o_i,c_r,c_i
#define ICB  8
#define NCHUNK 32     // 256/8

// static scratch (no allocations allowed)
__device__ float g_zpad[Bz * ICZ * ZPP];                 // ~71 MB
__device__ float g_wpack[NPLANE * HALF * ICZ * 9];       // ~3.5 MB
__device__ float g_bpack[NPLANE * HALF];
__device__ float g_gates[NPLANE * Bz * HALF * HWP];      // ~100 MB (activated)

// ---- packed fp32x2 helpers (sm_100+) --------------------------------------
__device__ __forceinline__ unsigned long long pack2(float a, float b) {
    unsigned long long r;
    asm("mov.b64 %0, {%1, %2};" : "=l"(r) : "f"(a), "f"(b));
    return r;
}
__device__ __forceinline__ void unpack2(unsigned long long v, float& a, float& b) {
    asm("mov.b64 {%0, %1}, %2;" : "=f"(a), "=f"(b) : "l"(v));
}
__device__ __forceinline__ void fma2(unsigned long long& d,
                                     unsigned long long a, unsigned long long b) {
    asm("fma.rn.f32x2 %0, %1, %2, %0;" : "+l"(d) : "l"(a), "l"(b));
}

// ---------------------------------------------------------------------------
// Kernel 1: build zero-padded z = concat(zr, zi) where
//   zr = [x[0:64], h[0:64]],  zi = [x[64:128], h[64:128]]
// layout g_zpad[b][ic][yy][xx], yy/xx in [0,66)
// ---------------------------------------------------------------------------
__global__ void fill_zpad(const float* __restrict__ x, const float* __restrict__ h) {
    int idx = blockIdx.x * blockDim.x + threadIdx.x;
    if (idx >= Bz * ICZ * ZPP) return;
    int b  = idx / (ICZ * ZPP);
    int r  = idx - b * (ICZ * ZPP);
    int ic = r / ZPP;
    int p  = r - ic * ZPP;
    int yy = p / ZP, xx = p - yy * ZP;
    float v = 0.0f;
    if (yy > 0 && yy < 65 && xx > 0 && xx < 65) {
        int sp = (yy - 1) * WW + (xx - 1);
        const float* src; int chn;
        if (ic < 64)       { src = x; chn = ic;        }
        else if (ic < 128) { src = h; chn = ic - 64;   }
        else if (ic < 192) { src = x; chn = ic - 64;   }   // x imag ch (ic-128)+64
        else               { src = h; chn = ic - 128;  }   // h imag ch (ic-192)+64
        v = src[(b * 128 + chn) * HWP + sp];
    }
    g_zpad[idx] = v;
}

// ---------------------------------------------------------------------------
// Kernel 2: pack complex-conv weights.
// plane = 2g+part, g in {0:i, 1:o, 2:c}, part 0=real 1=imag
//   real: [Wr | -Wi]   imag: [Wi | Wr]   over ic(0..255)
// layout g_wpack[plane][oc][ic][k]
// ---------------------------------------------------------------------------
__global__ void pack_w(const float* __restrict__ Wri, const float* __restrict__ Wii,
                       const float* __restrict__ Wro, const float* __restrict__ Wio,
                       const float* __restrict__ Wrc, const float* __restrict__ Wic,
                       const float* __restrict__ bri, const float* __restrict__ bii,
                       const float* __restrict__ bro, const float* __restrict__ bio,
                       const float* __restrict__ brc, const float* __restrict__ bic) {
    int idx = blockIdx.x * blockDim.x + threadIdx.x;
    if (idx < NPLANE * HALF) {
        int plane = idx >> 6, oc = idx & 63;
        int g = plane >> 1, part = plane & 1;
        const float* bp = part ? (g == 0 ? bii : (g == 1 ? bio : bic))
                               : (g == 0 ? bri : (g == 1 ? bro : brc));
        g_bpack[idx] = bp[oc];
    }
    if (idx >= NPLANE * HALF * ICZ * 9) return;
    int plane = idx / (HALF * ICZ * 9);
    int r     = idx - plane * (HALF * ICZ * 9);
    int oc = r / (ICZ * 9);
    int r2 = r - oc * (ICZ * 9);
    int ic = r2 / 9, k = r2 - ic * 9;
    int g = plane >> 1, part = plane & 1;
    const float* Wr = (g == 0) ? Wri : (g == 1) ? Wro : Wrc;
    const float* Wi = (g == 0) ? Wii : (g == 1) ? Wio : Wic;
    float v;
    if (ic < 128) {
        v = part ? Wi[(oc * 128 + ic) * 9 + k] : Wr[(oc * 128 + ic) * 9 + k];
    } else {
        int icc = ic - 128;
        v = part ? Wr[(oc * 128 + icc) * 9 + k] : -Wi[(oc * 128 + icc) * 9 + k];
    }
    g_wpack[idx] = v;
}

// ---------------------------------------------------------------------------
// Kernel 3: tiled direct conv, f32x2 packed FFMA, fused bias+activation.
// grid (16 tiles, 16 batch, 6 planes), 256 threads.
// Block computes 16x16 pixels x 64 oc.  Thread: 2x2 px x 16 oc (8 f32x2 pairs).
// ---------------------------------------------------------------------------
__global__ void __launch_bounds__(256, 2) conv_gates() {
    __shared__ __align__(16) float s_in[ICB][18][20];
    __shared__ __align__(16) float s_w[ICB * 9 * HALF];

    const int tile  = blockIdx.x;
    const int b     = blockIdx.y;
    const int plane = blockIdx.z;
    const int Y0 = (tile >> 2) << 4;
    const int X0 = (tile & 3) << 4;
    const int tid = threadIdx.x;
    const int oc0 = (tid >> 6) << 4;         // 0,16,32,48
    const int pid = tid & 63;
    const int py = (pid >> 3) << 1;          // 0..14 even
    const int px = (pid & 7) << 1;           // 0..14 even

    unsigned long long acc[4][8];
    #pragma unroll
    for (int p = 0; p < 4; ++p)
        #pragma unroll
        for (int j = 0; j < 8; ++j) acc[p][j] = 0ull;

    const float* zb = g_zpad + b * (ICZ * ZPP);
    const float* wp = g_wpack + plane * (HALF * ICZ * 9);

    for (int chunk = 0; chunk < NCHUNK; ++chunk) {
        const int ic0 = chunk * ICB;
        // cooperative smem loads
        for (int i = tid; i < ICB * 18 * 18; i += 256) {
            int ic = i / 324;
            int rem = i - ic * 324;
            int rr = rem / 18, cc = rem - rr * 18;
            s_in[ic][rr][cc] = zb[(ic0 + ic) * ZPP + (Y0 + rr) * ZP + (X0 + cc)];
        }
        for (int i = tid; i < ICB * 9 * HALF; i += 256) {
            int oc = i & 63;
            int rest = i >> 6;
            int ic = rest / 9, k = rest - ic * 9;
            s_w[i] = wp[(oc * ICZ + ic0 + ic) * 9 + k];
        }
        __syncthreads();

        #pragma unroll
        for (int ic = 0; ic < ICB; ++ic) {
            #pragma unroll
            for (int ky = 0; ky < 3; ++ky) {
                const float* rp0 = &s_in[ic][py + ky][px];
                const float* rp1 = rp0 + 20;
                float i00 = rp0[0], i01 = rp0[1], i02 = rp0[2], i03 = rp0[3];
                float i10 = rp1[0], i11 = rp1[1], i12 = rp1[2], i13 = rp1[3];
                #pragma unroll
                for (int kx = 0; kx < 3; ++kx) {
                    float a0 = (kx == 0) ? i00 : (kx == 1) ? i01 : i02;
                    float a1 = (kx == 0) ? i01 : (kx == 1) ? i02 : i03;
                    float b0 = (kx == 0) ? i10 : (kx == 1) ? i11 : i12;
                    float b1 = (kx == 0) ? i11 : (kx == 1) ? i12 : i13;
                    unsigned long long pa0 = pack2(a0, a0);
                    unsigned long long pa1 = pack2(a1, a1);
                    unsigned long long pb0 = pack2(b0, b0);
                    unsigned long long pb1 = pack2(b1, b1);
                    const ulonglong2* wv = reinterpret_cast<const ulonglong2*>(
                        &s_w[((ic * 3 + ky) * 3 + kx) * HALF + oc0]);
                    ulonglong2 w01 = wv[0], w23 = wv[1], w45 = wv[2], w67 = wv[3];
                    unsigned long long wj[8] = {w01.x, w01.y, w23.x, w23.y,
                                                w45.x, w45.y, w67.x, w67.y};
                    #pragma unroll
                    for (int j = 0; j < 8; ++j) {
                        fma2(acc[0][j], pa0, wj[j]);
                        fma2(acc[1][j], pa1, wj[j]);
                        fma2(acc[2][j], pb0, wj[j]);
                        fma2(acc[3][j], pb1, wj[j]);
                    }
                }
            }
        }
        __syncthreads();
    }

    // epilogue: bias + activation (sigmoid for planes 0-3, tanh for 4-5) + store
    const bool isTanh = (plane >= 4);
    float* Gout = g_gates + (plane * Bz + b) * (HALF * HWP);
    const int gy = Y0 + py, gx = X0 + px;
    #pragma unroll
    for (int j = 0; j < 8; ++j) {
        const int oc = oc0 + 2 * j;
        float blo = g_bpack[plane * HALF + oc];
        float bhi = g_bpack[plane * HALF + oc + 1];
        #pragma unroll
        for (int p = 0; p < 4; ++p) {
            float v0, v1;
            unpack2(acc[p][j], v0, v1);
            v0 += blo; v1 += bhi;
            if (isTanh) { v0 = tanhf(v0); v1 = tanhf(v1); }
            else        { v0 = 1.0f / (1.0f + expf(-v0));
                          v1 = 1.0f / (1.0f + expf(-v1)); }
            int yy = gy + (p >> 1), xx = gx + (p & 1);
            Gout[ oc      * HWP + yy * WW + xx] = v0;
            Gout[(oc + 1) * HWP + yy * WW + xx] = v1;
        }
    }
}

// ---------------------------------------------------------------------------
// Kernel 4: elementwise cell update.  out = [h_new | c_new], each NCHW with
// channel layout [real(64) | imag(64)].
// ---------------------------------------------------------------------------
__global__ void ewise(const float* __restrict__ x, const float* __restrict__ c_prev,
                      float* __restrict__ out) {
    int idx = blockIdx.x * blockDim.x + threadIdx.x;       // over Bz*HALF*HWP
    if (idx >= Bz * HALF * HWP) return;
    int b   = idx >> 18;                                   // /(64*4096)
    int r   = idx & 262143;
    int ch  = r >> 12;
    int pos = r & 4095;
    int base  = (b * 128 + ch) * HWP + pos;
    int basei = base + HALF * HWP;

    float xr = x[base],      xi = x[basei];
    float cr = c_prev[base], ci = c_prev[basei];

    const int GP = Bz * HALF * HWP;                        // plane stride
    float i_r  = g_gates[idx];
    float i_i  = g_gates[GP + idx];
    float o_r  = g_gates[2 * GP + idx];
    float o_i  = g_gates[3 * GP + idx];
    float ct_r = g_gates[4 * GP + idx];
    float ct_i = g_gates[5 * GP + idx];

    float cnr = xr * cr - xi * ci + i_r * ct_r - i_i * ct_i;
    float cni = xr * ci + xi * cr + i_r * ct_i + i_i * ct_r;
    float tr = tanhf(cnr), ti = tanhf(cni);
    float hr = o_r * tr - o_i * ti;
    float hi = o_r * ti + o_i * tr;

    const int HTOT = Bz * 128 * HWP;                       // 8388608
    out[base]          = hr;
    out[basei]         = hi;
    out[HTOT + base]   = cnr;
    out[HTOT + basei]  = cni;
}

// ---------------------------------------------------------------------------
extern "C" void kernel_launch(void* const* d_in, const int* in_sizes, int n_in,
                              void* d_out, int out_size) {
    const float* x      = (const float*)d_in[0];
    const float* h_prev = (const float*)d_in[1];
    const float* c_prev = (const float*)d_in[2];
    const float* Wr_i = (const float*)d_in[3];
    const float* Wi_i = (const float*)d_in[4];
    const float* br_i = (const float*)d_in[5];
    const float* bi_i = (const float*)d_in[6];
    // d_in[7..10] = f gate (unused by the reference output)
    const float* Wr_o = (const float*)d_in[11];
    const float* Wi_o = (const float*)d_in[12];
    const float* br_o = (const float*)d_in[13];
    const float* bi_o = (const float*)d_in[14];
    const float* Wr_c = (const float*)d_in[15];
    const float* Wi_c = (const float*)d_in[16];
    const float* br_c = (const float*)d_in[17];
    const float* bi_c = (const float*)d_in[18];

    const int NZ = Bz * ICZ * ZPP;
    fill_zpad<<<(NZ + 255) / 256, 256>>>(x, h_prev);

    const int NW = NPLANE * HALF * ICZ * 9;
    pack_w<<<(NW + 255) / 256, 256>>>(Wr_i, Wi_i, Wr_o, Wi_o, Wr_c, Wi_c,
                                      br_i, bi_i, br_o, bi_o, br_c, bi_c);

    conv_gates<<<dim3(16, Bz, NPLANE), 256>>>();

    const int NE = Bz * HALF * HWP;
    ewise<<<NE / 256, 256>>>(x, c_prev, (float*)d_out);
}

// round 9
// speedup vs baseline: 3.7757x; 3.7757x over previous
#include <cuda_runtime.h>
#include <cstdint>

// ---------------------------------------------------------------------------
// ConvLSTMCell (complex) via warp-level tf32 mma.sync implicit GEMM.
// (tcgen05 is rejected by the harness's ptxas target 'sm_103' -> HMMA path.)
//   GEMM: D[65536 px, 384] = A[px, 2304] * B[2304, 384]
//   K = 9 taps x 256 ic;  N = 6 gate planes (i_r,i_i,o_r,o_i,c_r,c_i) x 64 oc
// f-gate is dead code in the reference -> skipped.
// R8 fix: g_w2p was missing the n-tile axis (all 3 n-tiles read i-gate
// weights). Now [NCHUNKS][3][4096] with global n = ntile*128 + n_local.
// ---------------------------------------------------------------------------

#define Bz    16
#define ICZ   256
#define HWP   4096
#define ZP    66
#define ZPP   4356
#define NOC   384
#define NCHUNKS 72        // K chunks of 32

// static scratch
__device__ float g_zpad[Bz * ICZ * ZPP];          // tf32-rounded padded input (~71MB)
__device__ float g_w2p[NCHUNKS * 3 * 4096];       // weights, per (chunk, ntile) smem image
__device__ float g_b2[NOC];                       // biases
__device__ float g_gates[6 * Bz * 64 * HWP];      // activated gates (~100MB)

// ---------------- helpers ---------------------------------------------------
__device__ __forceinline__ uint32_t smem_u32(const void* p) {
    uint32_t a;
    asm("{ .reg .u64 t; cvta.to.shared.u64 t, %1; cvt.u32.u64 %0, t; }" : "=r"(a) : "l"(p));
    return a;
}
__device__ __forceinline__ float tf32r(float x) {
    uint32_t u; asm("cvt.rna.tf32.f32 %0, %1;" : "=r"(u) : "f"(x));
    return __uint_as_float(u);
}
__device__ __forceinline__ void cp4(uint32_t s, const void* g) {
    asm volatile("cp.async.ca.shared.global [%0], [%1], 4;" :: "r"(s), "l"(g) : "memory");
}
__device__ __forceinline__ void cp16(uint32_t s, const void* g) {
    asm volatile("cp.async.cg.shared.global [%0], [%1], 16;" :: "r"(s), "l"(g) : "memory");
}
__device__ __forceinline__ void cp_commit() {
    asm volatile("cp.async.commit_group;" ::: "memory");
}
__device__ __forceinline__ void cp_wait0() {
    asm volatile("cp.async.wait_group 0;" ::: "memory");
}
__device__ __forceinline__ void lds128(uint32_t* r, uint32_t a) {
    asm volatile("ld.shared.v4.b32 {%0,%1,%2,%3}, [%4];"
                 : "=r"(r[0]), "=r"(r[1]), "=r"(r[2]), "=r"(r[3]) : "r"(a));
}
__device__ __forceinline__ void lds64(uint32_t* r, uint32_t a) {
    asm volatile("ld.shared.v2.b32 {%0,%1}, [%2];" : "=r"(r[0]), "=r"(r[1]) : "r"(a));
}
__device__ __forceinline__ void mma8(float* d, const uint32_t* a, const uint32_t* b) {
    asm volatile("mma.sync.aligned.m16n8k8.row.col.f32.tf32.tf32.f32 "
                 "{%0,%1,%2,%3}, {%4,%5,%6,%7}, {%8,%9}, {%0,%1,%2,%3};"
                 : "+f"(d[0]), "+f"(d[1]), "+f"(d[2]), "+f"(d[3])
                 : "r"(a[0]), "r"(a[1]), "r"(a[2]), "r"(a[3]), "r"(b[0]), "r"(b[1]));
}
__device__ __forceinline__ float sigm(float v)  { return __fdividef(1.0f, 1.0f + __expf(-v)); }
__device__ __forceinline__ float tanh_(float v) { return 1.0f - __fdividef(2.0f, 1.0f + __expf(2.0f * v)); }

// ---------------------------------------------------------------------------
// Kernel 1: zero-padded, tf32-rounded z = [xr|hr|xi|hi]
// ---------------------------------------------------------------------------
__global__ void fill_zpad(const float* __restrict__ x, const float* __restrict__ h) {
    int idx = blockIdx.x * blockDim.x + threadIdx.x;
    if (idx >= Bz * ICZ * ZPP) return;
    int b  = idx / (ICZ * ZPP);
    int r  = idx - b * (ICZ * ZPP);
    int ic = r / ZPP;
    int p  = r - ic * ZPP;
    int yy = p / ZP, xx = p - yy * ZP;
    float v = 0.0f;
    if (yy > 0 && yy < 65 && xx > 0 && xx < 65) {
        int sp = (yy - 1) * 64 + (xx - 1);
        const float* src; int chn;
        if (ic < 64)       { src = x; chn = ic;       }
        else if (ic < 128) { src = h; chn = ic - 64;  }
        else if (ic < 192) { src = x; chn = ic - 64;  }
        else               { src = h; chn = ic - 128; }
        v = tf32r(src[(b * 128 + chn) * HWP + sp]);
    }
    g_zpad[idx] = v;
}

// ---------------------------------------------------------------------------
// Kernel 2: pack weights into the conv kernel's exact smem stage images,
// one 4096-float image per (chunk, ntile).
// Per chunk c (tap = c>>3, icb = (c&7)*32), image float f in [0,4096):
//   g=f>>10 (k8 group); n_local=(f>>3)&127; w=f&7; cc=w>>1; h=w&1;
//   ic = icb + g*8 + cc + 4h;  n = ntile*128 + n_local
// n = plane*64+oc, planes (i_r,i_i,o_r,o_i,c_r,c_i); real: [Wr|-Wi] imag: [Wi|Wr].
// ---------------------------------------------------------------------------
__global__ void pack_w(const float* __restrict__ Wri, const float* __restrict__ Wii,
                       const float* __restrict__ Wro, const float* __restrict__ Wio,
                       const float* __restrict__ Wrc, const float* __restrict__ Wic,
                       const float* __restrict__ bri, const float* __restrict__ bii,
                       const float* __restrict__ bro, const float* __restrict__ bio,
                       const float* __restrict__ brc, const float* __restrict__ bic) {
    int idx = blockIdx.x * blockDim.x + threadIdx.x;
    if (idx < NOC) {
        int plane = idx >> 6, oc = idx & 63;
        int g = plane >> 1, part = plane & 1;
        const float* bp = part ? (g == 0 ? bii : (g == 1 ? bio : bic))
                               : (g == 0 ? bri : (g == 1 ? bro : brc));
        g_b2[idx] = bp[oc];
    }
    if (idx >= NCHUNKS * 3 * 4096) return;
    int chunk = idx / 12288;
    int rem   = idx - chunk * 12288;
    int ntile = rem >> 12;
    int f     = rem & 4095;
    int g  = f >> 10;
    int r2 = f & 1023;
    int nl = r2 >> 3;
    int w  = r2 & 7;
    int cc = w >> 1, h = w & 1;
    int tap = chunk >> 3, icb = (chunk & 7) << 5;
    int ic  = icb + g * 8 + cc + 4 * h;           // 0..255
    int n   = ntile * 128 + nl;                   // 0..383
    int plane = n >> 6, oc = n & 63;
    int gate = plane >> 1, part = plane & 1;
    const float* Wr = (gate == 0) ? Wri : (gate == 1) ? Wro : Wrc;
    const float* Wi = (gate == 0) ? Wii : (gate == 1) ? Wio : Wic;
    float v;
    if (ic < 128) v = part ? Wi[(oc * 128 + ic) * 9 + tap] : Wr[(oc * 128 + ic) * 9 + tap];
    else {
        int icc = ic - 128;
        v = part ? Wr[(oc * 128 + icc) * 9 + tap] : -Wi[(oc * 128 + icc) * 9 + tap];
    }
    g_w2p[idx] = tf32r(v);
}

// ---------------------------------------------------------------------------
// Kernel 3: tf32 mma.sync GEMM conv.
// CTA 128 thr (4 warps), tile M=128 N=128, warp tile 64x64, K chunks of 32,
// cp.async double-buffered smem.  Epilogue: bias + activation -> g_gates.
// ---------------------------------------------------------------------------
#define AS_WORDS 5120            // 4 g * 64 rows * 20 words (16 data + 4 pad)
#define BS_WORDS 4096            // 4 g * 128 n * 8 words
#define STAGE_WORDS 9216
#define SMEM_BYTES (2 * STAGE_WORDS * 4)

__global__ void __launch_bounds__(128, 2)
conv_mma() {
    extern __shared__ float smem[];
    const uint32_t sbase = smem_u32(smem);
    const int tid  = threadIdx.x;
    const int lane = tid & 31, wid = tid >> 5;
    const int warp_m = wid & 1, warp_n = wid >> 1;
    const int ntile = blockIdx.x;                 // 0..2
    const int mtile = blockIdx.y;                 // 0..511
    const int b  = mtile >> 5;
    const int y0 = (mtile & 31) << 1;
    const float* zb = g_zpad + (size_t)b * (ICZ * ZPP);

    float acc[4][8][4];
    #pragma unroll
    for (int mt = 0; mt < 4; ++mt)
        #pragma unroll
        for (int nt = 0; nt < 8; ++nt)
            #pragma unroll
            for (int k = 0; k < 4; ++k) acc[mt][nt][k] = 0.0f;

    // per-thread A-gather constants: m = tid
    const int rowoff = tid >> 6;                  // 0/1
    const int xcol   = tid & 63;
    const int tt = tid >> 4, rr = tid & 15, rA = rr & 7, half = rr >> 3;
    const uint32_t a_sts_base = (uint32_t)((tt * 8 + rA) * 20 + half) * 4;  // bytes

    // ---- chunk loader (cp.async) ----
    auto load_chunk = [&](int c, int stage) {
        const int tap = c >> 3, icb = (c & 7) << 5;
        const int ky = (tap >= 6) ? 2 : (tap >= 3) ? 1 : 0;
        const int kx = tap - ky * 3;
        const float* abase = zb + (size_t)icb * ZPP + (y0 + ky + rowoff) * ZP + kx + xcol;
        const uint32_t as = sbase + (uint32_t)stage * (STAGE_WORDS * 4) + a_sts_base;
        #pragma unroll
        for (int j = 0; j < 32; ++j) {
            const int g = j >> 3, w = j & 7, cc = w & 3, kh = w >> 2;
            cp4(as + (uint32_t)(g * 1280 + cc * 4 + 2 * kh) * 4, abase + j * ZPP);
        }
        const float4* bsrc = reinterpret_cast<const float4*>(
                                 g_w2p + ((size_t)c * 3 + ntile) * 4096) + tid;
        const uint32_t bs = sbase + (uint32_t)stage * (STAGE_WORDS * 4) + AS_WORDS * 4 + tid * 16;
        #pragma unroll
        for (int j = 0; j < 8; ++j)
            cp16(bs + (uint32_t)j * 2048, bsrc + j * 128);
        cp_commit();
    };

    // ---- compute one chunk from smem stage ----
    auto compute = [&](int stage) {
        const uint32_t as = sbase + (uint32_t)stage * (STAGE_WORDS * 4);
        const uint32_t bs = as + AS_WORDS * 4;
        const int rl = lane >> 2, cl = lane & 3;
        #pragma unroll
        for (int g = 0; g < 4; ++g) {
            uint32_t af[4][4];
            #pragma unroll
            for (int mt = 0; mt < 4; ++mt) {
                uint32_t addr = as + (uint32_t)(((g * 64 + (warp_m * 4 + mt) * 8 + rl) * 20
                                                + cl * 4) * 4);
                lds128(af[mt], addr);
            }
            uint32_t bf[8][2];
            #pragma unroll
            for (int nt = 0; nt < 8; ++nt) {
                int n = warp_n * 64 + nt * 8 + rl;
                uint32_t addr = bs + (uint32_t)(((g * 128 + n) * 8 + cl * 2) * 4);
                lds64(bf[nt], addr);
            }
            #pragma unroll
            for (int mt = 0; mt < 4; ++mt)
                #pragma unroll
                for (int nt = 0; nt < 8; ++nt)
                    mma8(acc[mt][nt], af[mt], bf[nt]);
        }
    };

    load_chunk(0, 0);
    cp_wait0();
    __syncthreads();

    for (int c = 0; c < NCHUNKS; ++c) {
        const int s = c & 1;
        if (c + 1 < NCHUNKS) load_chunk(c + 1, s ^ 1);
        compute(s);
        if (c + 1 < NCHUNKS) cp_wait0();
        __syncthreads();
    }

    // ---- epilogue: bias + activation -> g_gates[plane][b][oc][pos] ----
    const int basepos = (mtile & 31) * 128;
    const int r0 = warp_m * 64 + (lane >> 2);
    const int c0 = ntile * 128 + warp_n * 64 + 2 * (lane & 3);
    #pragma unroll
    for (int nt = 0; nt < 8; ++nt) {
        const int n0 = c0 + nt * 8;
        const float b0v = g_b2[n0], b1v = g_b2[n0 + 1];
        const int pl0 = n0 >> 6, oc0 = n0 & 63;
        const int pl1 = (n0 + 1) >> 6, oc1 = (n0 + 1) & 63;
        float* g0 = g_gates + (size_t)(pl0 * Bz + b) * 262144 + oc0 * HWP + basepos;
        float* g1 = g_gates + (size_t)(pl1 * Bz + b) * 262144 + oc1 * HWP + basepos;
        #pragma unroll
        for (int mt = 0; mt < 4; ++mt) {
            #pragma unroll
            for (int k = 0; k < 4; ++k) {
                const int mrow = r0 + mt * 16 + ((k & 2) ? 8 : 0);
                float v = acc[mt][nt][k] + ((k & 1) ? b1v : b0v);
                const int pl = (k & 1) ? pl1 : pl0;
                v = (pl >= 4) ? tanh_(v) : sigm(v);
                ((k & 1) ? g1 : g0)[mrow] = v;
            }
        }
    }
}

// ---------------------------------------------------------------------------
// Kernel 4: elementwise cell update
// ---------------------------------------------------------------------------
__global__ void ewise(const float* __restrict__ x, const float* __restrict__ c_prev,
                      float* __restrict__ out) {
    int idx = blockIdx.x * blockDim.x + threadIdx.x;
    if (idx >= Bz * 64 * HWP) return;
    int b   = idx >> 18;
    int r   = idx & 262143;
    int ch  = r >> 12;
    int pos = r & 4095;
    int base  = (b * 128 + ch) * HWP + pos;
    int basei = base + 64 * HWP;

    float xr = x[base],      xi = x[basei];
    float cr = c_prev[base], ci = c_prev[basei];

    const int GP = Bz * 64 * HWP;
    float i_r  = g_gates[idx];
    float i_i  = g_gates[GP + idx];
    float o_r  = g_gates[2 * GP + idx];
    float o_i  = g_gates[3 * GP + idx];
    float ct_r = g_gates[4 * GP + idx];
    float ct_i = g_gates[5 * GP + idx];

    float cnr = xr * cr - xi * ci + i_r * ct_r - i_i * ct_i;
    float cni = xr * ci + xi * cr + i_r * ct_i + i_i * ct_r;
    float tr = tanhf(cnr), ti = tanhf(cni);
    float hr = o_r * tr - o_i * ti;
    float hi = o_r * ti + o_i * tr;

    const int HTOT = Bz * 128 * HWP;
    out[base]          = hr;
    out[basei]         = hi;
    out[HTOT + base]   = cnr;
    out[HTOT + basei]  = cni;
}

// ---------------------------------------------------------------------------
extern "C" void kernel_launch(void* const* d_in, const int* in_sizes, int n_in,
                              void* d_out, int out_size) {
    const float* x      = (const float*)d_in[0];
    const float* h_prev = (const float*)d_in[1];
    const float* c_prev = (const float*)d_in[2];
    const float* Wr_i = (const float*)d_in[3];
    const float* Wi_i = (const float*)d_in[4];
    const float* br_i = (const float*)d_in[5];
    const float* bi_i = (const float*)d_in[6];
    // d_in[7..10] = f gate (unused by the reference output)
    const float* Wr_o = (const float*)d_in[11];
    const float* Wi_o = (const float*)d_in[12];
    const float* br_o = (const float*)d_in[13];
    const float* bi_o = (const float*)d_in[14];
    const float* Wr_c = (const float*)d_in[15];
    const float* Wi_c = (const float*)d_in[16];
    const float* br_c = (const float*)d_in[17];
    const float* bi_c = (const float*)d_in[18];

    cudaFuncSetAttribute(conv_mma, cudaFuncAttributeMaxDynamicSharedMemorySize, SMEM_BYTES);

    const int NZ = Bz * ICZ * ZPP;
    fill_zpad<<<(NZ + 255) / 256, 256>>>(x, h_prev);

    const int NW = NCHUNKS * 3 * 4096;
    pack_w<<<(NW + 255) / 256, 256>>>(Wr_i, Wi_i, Wr_o, Wi_o, Wr_c, Wi_c,
                                      br_i, bi_i, br_o, bi_o, br_c, bi_c);

    conv_mma<<<dim3(3, 512), 128, SMEM_BYTES>>>();

    const int NE = Bz * 64 * HWP;
    ewise<<<NE / 256, 256>>>(x, c_prev, (float*)d_out);
}